// round 3
// baseline (speedup 1.0000x reference)
#include <cuda_runtime.h>
#include <math.h>

// Problem constants (fixed by the dataset)
#define D_DIM 768
#define S_LEN 4096
#define B_BATCH 4
#define M_TOT (B_BATCH * S_LEN)            // 16384
#define BSD (B_BATCH * S_LEN * D_DIM)      // 12,582,912 floats
#define SS  ((long long)S_LEN * S_LEN)     // 16,777,216 per batch

// Static device scratch (no allocations allowed in kernel_launch)
__device__ float g_Q[BSD];
__device__ float g_K[BSD];
__device__ float g_V[BSD];
__device__ float g_Y[BSD];
__device__ float g_Yp[BSD];
__device__ float g_att[(size_t)B_BATCH * S_LEN * S_LEN];   // 256 MB

// ---------------------------------------------------------------------------
// SGEMM: C[M,N] = A[M,K] @ op(B) + bias
//   B_IS_NT = true : B stored [N,K] row-major (C = A*B^T)   -- projections, Q*K^T
//   B_IS_NT = false: B stored [K,N] row-major (C = A*B)     -- att*V
// 128x128 tile, BK=8, 256 threads, 8x8 per thread (2x 4-wide fragments).
// All dims here are multiples of the tile sizes (16384/4096/768 % 128 == 0,
// K % 8 == 0), so no bounds checks.
// ---------------------------------------------------------------------------
#define BM 128
#define BN 128
#define BK 8
#define LDS 132   // padded row: 132 floats = 528 B, 16B-aligned rows, bank-shift 4

template <bool B_IS_NT>
__global__ void __launch_bounds__(256)
gemm_kernel(const float* __restrict__ A, const float* __restrict__ Bm,
            const float* __restrict__ bias, float* __restrict__ C,
            int M, int N, int K,
            long long strideA, long long strideB, long long strideC)
{
    const int bz = blockIdx.z;
    A  += (long long)bz * strideA;
    Bm += (long long)bz * strideB;
    C  += (long long)bz * strideC;

    __shared__ __align__(16) float As[BK][LDS];
    __shared__ __align__(16) float Bs[BK][LDS];

    const int tid = threadIdx.x;
    const int tx = tid & 15;          // 0..15 -> output cols
    const int ty = tid >> 4;          // 0..15 -> output rows
    const int m0 = blockIdx.y * BM;
    const int n0 = blockIdx.x * BN;

    // A-loader (and B-loader in NT mode): 2 threads per row, float4 along K
    const int lrow = tid >> 1;        // 0..127
    const int lk   = (tid & 1) * 4;   // 0 or 4

    // B-loader in NN mode: 32 threads per k-row, float4 along N
    const int bk = tid >> 5;          // 0..7
    const int bn = (tid & 31) * 4;    // 0..124

    float acc[8][8];
    #pragma unroll
    for (int i = 0; i < 8; i++)
        #pragma unroll
        for (int j = 0; j < 8; j++) acc[i][j] = 0.0f;

    for (int k0 = 0; k0 < K; k0 += BK) {
        // --- load A tile (transpose into As[k][m]) ---
        float4 av = *(const float4*)&A[(long long)(m0 + lrow) * K + k0 + lk];
        As[lk + 0][lrow] = av.x;
        As[lk + 1][lrow] = av.y;
        As[lk + 2][lrow] = av.z;
        As[lk + 3][lrow] = av.w;

        if (B_IS_NT) {
            float4 bv = *(const float4*)&Bm[(long long)(n0 + lrow) * K + k0 + lk];
            Bs[lk + 0][lrow] = bv.x;
            Bs[lk + 1][lrow] = bv.y;
            Bs[lk + 2][lrow] = bv.z;
            Bs[lk + 3][lrow] = bv.w;
        } else {
            float4 bv = *(const float4*)&Bm[(long long)(k0 + bk) * N + n0 + bn];
            *(float4*)&Bs[bk][bn] = bv;
        }
        __syncthreads();

        #pragma unroll
        for (int kk = 0; kk < BK; kk++) {
            float4 a0 = *(const float4*)&As[kk][ty * 4];
            float4 a1 = *(const float4*)&As[kk][64 + ty * 4];
            float4 b0 = *(const float4*)&Bs[kk][tx * 4];
            float4 b1 = *(const float4*)&Bs[kk][64 + tx * 4];
            float a[8] = {a0.x, a0.y, a0.z, a0.w, a1.x, a1.y, a1.z, a1.w};
            float b[8] = {b0.x, b0.y, b0.z, b0.w, b1.x, b1.y, b1.z, b1.w};
            #pragma unroll
            for (int i = 0; i < 8; i++)
                #pragma unroll
                for (int j = 0; j < 8; j++)
                    acc[i][j] += a[i] * b[j];
        }
        __syncthreads();
    }

    // bias fragments (columns)
    float bfr[8];
    #pragma unroll
    for (int j = 0; j < 8; j++) bfr[j] = 0.0f;
    if (bias) {
        #pragma unroll
        for (int j = 0; j < 4; j++) {
            bfr[j]     = bias[n0 + tx * 4 + j];
            bfr[j + 4] = bias[n0 + 64 + tx * 4 + j];
        }
    }

    #pragma unroll
    for (int i = 0; i < 8; i++) {
        int r = m0 + ((i < 4) ? (ty * 4 + i) : (64 + ty * 4 + (i - 4)));
        float4 o0 = make_float4(acc[i][0] + bfr[0], acc[i][1] + bfr[1],
                                acc[i][2] + bfr[2], acc[i][3] + bfr[3]);
        float4 o1 = make_float4(acc[i][4] + bfr[4], acc[i][5] + bfr[5],
                                acc[i][6] + bfr[6], acc[i][7] + bfr[7]);
        *(float4*)&C[(long long)r * N + n0 + tx * 4]      = o0;
        *(float4*)&C[(long long)r * N + n0 + 64 + tx * 4] = o1;
    }
}

// ---------------------------------------------------------------------------
// Row softmax over att rows of length S_LEN (scale applied to logits here).
// One block per row; full row staged in smem (16 KB) -> one global R + one W.
// ---------------------------------------------------------------------------
__global__ void __launch_bounds__(256)
softmax_kernel(float* __restrict__ att, float scale)
{
    __shared__ float buf[S_LEN];
    __shared__ float red[256];
    const long long row = blockIdx.x;
    float* p = att + row * S_LEN;
    const int tid = threadIdx.x;

    float mx = -1e30f;
    for (int i = tid; i < S_LEN; i += 256) {
        float v = p[i] * scale;
        buf[i] = v;
        mx = fmaxf(mx, v);
    }
    red[tid] = mx;
    __syncthreads();
    for (int s = 128; s > 0; s >>= 1) {
        if (tid < s) red[tid] = fmaxf(red[tid], red[tid + s]);
        __syncthreads();
    }
    mx = red[0];
    __syncthreads();

    float sum = 0.0f;
    for (int i = tid; i < S_LEN; i += 256) {
        float e = __expf(buf[i] - mx);
        buf[i] = e;
        sum += e;
    }
    red[tid] = sum;
    __syncthreads();
    for (int s = 128; s > 0; s >>= 1) {
        if (tid < s) red[tid] += red[tid + s];
        __syncthreads();
    }
    float inv = 1.0f / red[0];

    for (int i = tid; i < S_LEN; i += 256)
        p[i] = buf[i] * inv;
}

// ---------------------------------------------------------------------------
// The reference's transpose(0,2,1).reshape(B,S,D) element permutation:
//   Yp[b].flat[n] = Y[b, n % S, n / S]   (n = i*D + j)
// ---------------------------------------------------------------------------
__global__ void __launch_bounds__(256)
permute_kernel(const float* __restrict__ Y, float* __restrict__ Yp)
{
    long long idx = (long long)blockIdx.x * 256 + threadIdx.x;
    if (idx >= (long long)BSD) return;
    long long b = idx / ((long long)S_LEN * D_DIM);
    long long n = idx % ((long long)S_LEN * D_DIM);
    long long s = n % S_LEN;
    long long d = n / S_LEN;
    Yp[idx] = Y[b * (long long)S_LEN * D_DIM + s * D_DIM + d];
}

// ---------------------------------------------------------------------------
extern "C" void kernel_launch(void* const* d_in, const int* in_sizes, int n_in,
                              void* d_out, int out_size)
{
    const float* x  = (const float*)d_in[0];
    const float* Wq = (const float*)d_in[1];
    const float* bq = (const float*)d_in[2];
    const float* Wk = (const float*)d_in[3];
    const float* bk = (const float*)d_in[4];
    const float* Wv = (const float*)d_in[5];
    const float* bv = (const float*)d_in[6];
    const float* Wc = (const float*)d_in[7];
    const float* bc = (const float*)d_in[8];
    float* out = (float*)d_out;

    float *Q, *Kb, *V, *Y, *Yp, *att;
    cudaGetSymbolAddress((void**)&Q,   g_Q);
    cudaGetSymbolAddress((void**)&Kb,  g_K);
    cudaGetSymbolAddress((void**)&V,   g_V);
    cudaGetSymbolAddress((void**)&Y,   g_Y);
    cudaGetSymbolAddress((void**)&Yp,  g_Yp);
    cudaGetSymbolAddress((void**)&att, g_att);

    const float scale = 0.03608439182435161f;   // 768^-0.5
    dim3 blk(256);

    // QKV projections: [16384,768] = x[16384,768] @ W^T + b
    dim3 gp(D_DIM / BN, M_TOT / BM, 1);                 // (6,128,1)
    gemm_kernel<true><<<gp, blk>>>(x, Wq, bq, Q,  M_TOT, D_DIM, D_DIM, 0, 0, 0);
    gemm_kernel<true><<<gp, blk>>>(x, Wk, bk, Kb, M_TOT, D_DIM, D_DIM, 0, 0, 0);
    gemm_kernel<true><<<gp, blk>>>(x, Wv, bv, V,  M_TOT, D_DIM, D_DIM, 0, 0, 0);

    // att[b] = Q[b] @ K[b]^T   (scale folded into softmax)
    dim3 ga(S_LEN / BN, S_LEN / BM, B_BATCH);           // (32,32,4)
    gemm_kernel<true><<<ga, blk>>>(Q, Kb, nullptr, att,
                                   S_LEN, S_LEN, D_DIM,
                                   (long long)S_LEN * D_DIM,
                                   (long long)S_LEN * D_DIM, SS);

    softmax_kernel<<<B_BATCH * S_LEN, blk>>>(att, scale);

    // Y[b] = att[b] @ V[b]   (NN)
    dim3 gy(D_DIM / BN, S_LEN / BM, B_BATCH);           // (6,32,4)
    gemm_kernel<false><<<gy, blk>>>(att, V, nullptr, Y,
                                    S_LEN, D_DIM, S_LEN,
                                    SS, (long long)S_LEN * D_DIM,
                                    (long long)S_LEN * D_DIM);

    // transpose(0,2,1).reshape permutation
    permute_kernel<<<(BSD + 255) / 256, blk>>>(Y, Yp);

    // output projection -> d_out
    gemm_kernel<true><<<gp, blk>>>(Yp, Wc, bc, out, M_TOT, D_DIM, D_DIM, 0, 0, 0);
}

// round 6
// speedup vs baseline: 2.0987x; 2.0987x over previous
#include <cuda_runtime.h>
#include <cuda_bf16.h>
#include <stdint.h>

// ---------------------------------------------------------------------------
// Problem constants
// ---------------------------------------------------------------------------
#define D_DIM 768
#define S_LEN 4096
#define B_BATCH 4
#define M_TOT (B_BATCH * S_LEN)            // 16384
#define BSD (B_BATCH * S_LEN * D_DIM)
#define SSLL ((long long)S_LEN * S_LEN)

// Static device scratch
__device__ __align__(256) float g_Q[BSD];
__device__ __align__(256) float g_K[BSD];
__device__ __align__(256) float g_V[BSD];
__device__ __align__(256) float g_Vt[BSD];
__device__ __align__(256) float g_Y[BSD];
__device__ __align__(256) float g_Yp[BSD];
__device__ __align__(256) float g_att[(size_t)B_BATCH * S_LEN * S_LEN];

// ---------------------------------------------------------------------------
// Warp-MMA GEMM: C[M,N] = A[M,K] @ B^T + bias   (A [M,K], B [N,K] row-major fp32)
// 3xBF16 split (hi*hi + hi*lo + lo*hi), fp32 accumulate in registers.
// Block tile 128x128, BK=32 fp32. 8 warps (2m x 4n), warp tile 64x32,
// mma.sync.aligned.m16n8k16.row.col.f32.bf16.bf16.f32 + ldmatrix.x4.
// Smem: 4 matrices (Ahi/Alo/Bhi/Blo), 128 rows x 32 bf16, row stride 80B
// (conflict-free ldmatrix), double buffered.
// ---------------------------------------------------------------------------
#define BM 128
#define BN 128
#define BKF 32
#define LDSROW 80
#define MAT_BYTES (128 * LDSROW)            // 10240
#define OFF_AHI 0
#define OFF_ALO (1 * MAT_BYTES)
#define OFF_BHI (2 * MAT_BYTES)
#define OFF_BLO (3 * MAT_BYTES)
#define STAGE_BYTES (4 * MAT_BYTES)         // 40960
#define GSMEM (2 * STAGE_BYTES)             // 81920

__device__ __forceinline__ uint32_t smem_u32(const void* p) {
    uint32_t a;
    asm("{ .reg .u64 t; cvta.to.shared.u64 t, %1; cvt.u32.u64 %0, t; }" : "=r"(a) : "l"(p));
    return a;
}

__device__ __forceinline__ void ldmx4(uint32_t addr, uint32_t* r) {
    asm volatile("ldmatrix.sync.aligned.m8n8.x4.shared.b16 {%0,%1,%2,%3}, [%4];"
                 : "=r"(r[0]), "=r"(r[1]), "=r"(r[2]), "=r"(r[3]) : "r"(addr));
}

__device__ __forceinline__ void mma16816(float* d, const uint32_t* a, uint32_t b0, uint32_t b1) {
    asm volatile("mma.sync.aligned.m16n8k16.row.col.f32.bf16.bf16.f32 "
                 "{%0,%1,%2,%3}, {%4,%5,%6,%7}, {%8,%9}, {%0,%1,%2,%3};"
                 : "+f"(d[0]), "+f"(d[1]), "+f"(d[2]), "+f"(d[3])
                 : "r"(a[0]), "r"(a[1]), "r"(a[2]), "r"(a[3]), "r"(b0), "r"(b1));
}

// Split fp32x4 into hi/lo bf16x4 and store to padded smem rows.
__device__ __forceinline__ void split_sts(char* hi, char* lo, int r, int kq, float4 v) {
    __nv_bfloat162 h01 = __float22bfloat162_rn(make_float2(v.x, v.y));
    __nv_bfloat162 h23 = __float22bfloat162_rn(make_float2(v.z, v.w));
    float2 f01 = __bfloat1622float2(h01);
    float2 f23 = __bfloat1622float2(h23);
    __nv_bfloat162 l01 = __float22bfloat162_rn(make_float2(v.x - f01.x, v.y - f01.y));
    __nv_bfloat162 l23 = __float22bfloat162_rn(make_float2(v.z - f23.x, v.w - f23.y));
    uint2 hv, lv;
    hv.x = *(uint32_t*)&h01; hv.y = *(uint32_t*)&h23;
    lv.x = *(uint32_t*)&l01; lv.y = *(uint32_t*)&l23;
    int off = r * LDSROW + kq * 8;
    *(uint2*)(hi + off) = hv;
    *(uint2*)(lo + off) = lv;
}

__global__ void __launch_bounds__(256, 1)
gemm_mma(const float* __restrict__ A, const float* __restrict__ Bm,
         const float* __restrict__ bias, float* __restrict__ C,
         int N, int K, long long sA, long long sB, long long sC)
{
    extern __shared__ char sm[];
    const uint32_t sb = smem_u32(sm);
    const int tid = threadIdx.x;
    const int wid = tid >> 5;
    const int lane = tid & 31;
    const int wm = wid >> 2;          // 0..1
    const int wn = wid & 3;           // 0..3
    const int m0 = blockIdx.y * BM;
    const int n0 = blockIdx.x * BN;
    A  += (long long)blockIdx.z * sA;
    Bm += (long long)blockIdx.z * sB;
    C  += (long long)blockIdx.z * sC;

    const float* Ag = A + (long long)m0 * K;
    const float* Bg = Bm + (long long)n0 * K;

    // producer indices: thread covers rows pr+32i (i=0..3), fp32 col group pk (4 floats)
    const int pr = tid >> 3;          // 0..31
    const int pk = tid & 7;           // 0..7

    // ldmatrix per-lane offset (same formula for A and B x4 loads)
    const uint32_t lmo = (uint32_t)((lane & 15) * LDSROW + (lane >> 4) * 16);

    float acc[4][4][4];
    #pragma unroll
    for (int i = 0; i < 4; i++)
        #pragma unroll
        for (int j = 0; j < 4; j++)
            #pragma unroll
            for (int q = 0; q < 4; q++) acc[i][j][q] = 0.0f;

    const int KT = K / BKF;

    // ---- prologue: fill stage 0 ----
    {
        char* st = sm;
        #pragma unroll
        for (int i = 0; i < 4; i++) {
            int r = pr + 32 * i;
            float4 va = *(const float4*)(Ag + (long long)r * K + pk * 4);
            float4 vb = *(const float4*)(Bg + (long long)r * K + pk * 4);
            split_sts(st + OFF_AHI, st + OFF_ALO, r, pk, va);
            split_sts(st + OFF_BHI, st + OFF_BLO, r, pk, vb);
        }
    }
    __syncthreads();

    for (int kt = 0; kt < KT; kt++) {
        const int cur = kt & 1;
        const int nxt = cur ^ 1;
        const bool hasNext = (kt + 1) < KT;

        // ---- issue global loads for next stage ----
        float4 av[4], bv[4];
        if (hasNext) {
            const float* Ap = Ag + (kt + 1) * BKF;
            const float* Bp = Bg + (kt + 1) * BKF;
            #pragma unroll
            for (int i = 0; i < 4; i++) {
                int r = pr + 32 * i;
                av[i] = *(const float4*)(Ap + (long long)r * K + pk * 4);
                bv[i] = *(const float4*)(Bp + (long long)r * K + pk * 4);
            }
        }

        // ---- MMA on current stage ----
        const uint32_t stb = sb + (uint32_t)cur * STAGE_BYTES;
        #pragma unroll
        for (int ks = 0; ks < 2; ks++) {
            const uint32_t kb = (uint32_t)(ks * 32);   // 16 bf16 * 2B
            uint32_t ah[4][4], al[4][4];
            uint32_t bh[2][4], bl[2][4];
            #pragma unroll
            for (int mt = 0; mt < 4; mt++) {
                uint32_t rowb = (uint32_t)((wm * 64 + mt * 16) * LDSROW);
                ldmx4(stb + OFF_AHI + rowb + lmo + kb, ah[mt]);
                ldmx4(stb + OFF_ALO + rowb + lmo + kb, al[mt]);
            }
            #pragma unroll
            for (int g = 0; g < 2; g++) {
                uint32_t rowb = (uint32_t)((wn * 32 + g * 16) * LDSROW);
                ldmx4(stb + OFF_BHI + rowb + lmo + kb, bh[g]);
                ldmx4(stb + OFF_BLO + rowb + lmo + kb, bl[g]);
            }
            #pragma unroll
            for (int mt = 0; mt < 4; mt++) {
                #pragma unroll
                for (int nt = 0; nt < 4; nt++) {
                    const int g = nt >> 1, h = nt & 1;
                    mma16816(acc[mt][nt], ah[mt], bh[g][h], bh[g][h + 2]); // hi*hi
                    mma16816(acc[mt][nt], ah[mt], bl[g][h], bl[g][h + 2]); // hi*lo
                    mma16816(acc[mt][nt], al[mt], bh[g][h], bh[g][h + 2]); // lo*hi
                }
            }
        }

        // ---- convert + store next stage ----
        if (hasNext) {
            char* st = sm + nxt * STAGE_BYTES;
            #pragma unroll
            for (int i = 0; i < 4; i++) {
                int r = pr + 32 * i;
                split_sts(st + OFF_AHI, st + OFF_ALO, r, pk, av[i]);
                split_sts(st + OFF_BHI, st + OFF_BLO, r, pk, bv[i]);
            }
        }
        __syncthreads();
    }

    // ---- epilogue ----
    const int rbase = m0 + wm * 64 + (lane >> 2);
    const int cbase = n0 + wn * 32 + (lane & 3) * 2;
    #pragma unroll
    for (int nt = 0; nt < 4; nt++) {
        const int c = cbase + nt * 8;
        float b0 = 0.0f, b1 = 0.0f;
        if (bias) { b0 = bias[c]; b1 = bias[c + 1]; }
        #pragma unroll
        for (int mt = 0; mt < 4; mt++) {
            const int r = rbase + mt * 16;
            float2 v0 = make_float2(acc[mt][nt][0] + b0, acc[mt][nt][1] + b1);
            float2 v1 = make_float2(acc[mt][nt][2] + b0, acc[mt][nt][3] + b1);
            *(float2*)&C[(long long)r * N + c]       = v0;
            *(float2*)&C[(long long)(r + 8) * N + c] = v1;
        }
    }
}

// ---------------------------------------------------------------------------
// Row softmax (scale folded in). One block per row, row staged in smem.
// ---------------------------------------------------------------------------
__global__ void __launch_bounds__(256)
softmax_kernel(float* __restrict__ att, float scale)
{
    __shared__ float buf[S_LEN];
    __shared__ float red[256];
    const long long row = blockIdx.x;
    float* p = att + row * S_LEN;
    const int tid = threadIdx.x;

    float mx = -1e30f;
    for (int i = tid; i < S_LEN; i += 256) {
        float v = p[i] * scale;
        buf[i] = v;
        mx = fmaxf(mx, v);
    }
    red[tid] = mx;
    __syncthreads();
    for (int s = 128; s > 0; s >>= 1) {
        if (tid < s) red[tid] = fmaxf(red[tid], red[tid + s]);
        __syncthreads();
    }
    mx = red[0];
    __syncthreads();

    float sum = 0.0f;
    for (int i = tid; i < S_LEN; i += 256) {
        float e = __expf(buf[i] - mx);
        buf[i] = e;
        sum += e;
    }
    red[tid] = sum;
    __syncthreads();
    for (int s = 128; s > 0; s >>= 1) {
        if (tid < s) red[tid] += red[tid + s];
        __syncthreads();
    }
    float inv = 1.0f / red[0];
    for (int i = tid; i < S_LEN; i += 256)
        p[i] = buf[i] * inv;
}

// ---------------------------------------------------------------------------
// Per-batch tiled transpose: src [R,C] -> dst [C,R] (both row-major), batch z.
// Used for V^T and for the reference's transpose(0,2,1).reshape permutation.
// ---------------------------------------------------------------------------
__global__ void __launch_bounds__(256)
transpose_kernel(const float* __restrict__ src, float* __restrict__ dst, int R, int C)
{
    __shared__ float t[32][33];
    const long long bofs = (long long)blockIdx.z * R * C;
    src += bofs; dst += bofs;
    int c0 = blockIdx.x * 32, r0 = blockIdx.y * 32;
    for (int i = threadIdx.y; i < 32; i += 8)
        t[i][threadIdx.x] = src[(long long)(r0 + i) * C + c0 + threadIdx.x];
    __syncthreads();
    for (int i = threadIdx.y; i < 32; i += 8)
        dst[(long long)(c0 + i) * R + r0 + threadIdx.x] = t[threadIdx.x][i];
}

// ---------------------------------------------------------------------------
extern "C" void kernel_launch(void* const* d_in, const int* in_sizes, int n_in,
                              void* d_out, int out_size)
{
    const float* x  = (const float*)d_in[0];
    const float* Wq = (const float*)d_in[1];
    const float* bq = (const float*)d_in[2];
    const float* Wk = (const float*)d_in[3];
    const float* bk = (const float*)d_in[4];
    const float* Wv = (const float*)d_in[5];
    const float* bv = (const float*)d_in[6];
    const float* Wc = (const float*)d_in[7];
    const float* bc = (const float*)d_in[8];
    float* out = (float*)d_out;

    float *Q, *Kb, *V, *Vt, *Y, *Yp, *att;
    cudaGetSymbolAddress((void**)&Q,   g_Q);
    cudaGetSymbolAddress((void**)&Kb,  g_K);
    cudaGetSymbolAddress((void**)&V,   g_V);
    cudaGetSymbolAddress((void**)&Vt,  g_Vt);
    cudaGetSymbolAddress((void**)&Y,   g_Y);
    cudaGetSymbolAddress((void**)&Yp,  g_Yp);
    cudaGetSymbolAddress((void**)&att, g_att);

    cudaFuncSetAttribute(gemm_mma, cudaFuncAttributeMaxDynamicSharedMemorySize, GSMEM);

    const float scale = 0.03608439182435161f;   // 768^-0.5
    const long long sd = (long long)S_LEN * D_DIM;
    dim3 blk(256);
    dim3 tblk(32, 8);

    // QKV projections: [16384,768] = x @ W^T + b
    dim3 gp(D_DIM / BN, M_TOT / BM, 1);                  // (6,128,1)
    gemm_mma<<<gp, blk, GSMEM>>>(x, Wq, bq, Q,  D_DIM, D_DIM, 0, 0, 0);
    gemm_mma<<<gp, blk, GSMEM>>>(x, Wk, bk, Kb, D_DIM, D_DIM, 0, 0, 0);
    gemm_mma<<<gp, blk, GSMEM>>>(x, Wv, bv, V,  D_DIM, D_DIM, 0, 0, 0);

    // att[b] = Q[b] @ K[b]^T
    dim3 ga(S_LEN / BN, S_LEN / BM, B_BATCH);            // (32,32,4)
    gemm_mma<<<ga, blk, GSMEM>>>(Q, Kb, nullptr, att, S_LEN, D_DIM, sd, sd, SSLL);

    softmax_kernel<<<M_TOT, blk>>>(att, scale);

    // V^T per batch: [S,D] -> [D,S]
    dim3 gt(D_DIM / 32, S_LEN / 32, B_BATCH);            // (24,128,4)
    transpose_kernel<<<gt, tblk>>>(V, Vt, S_LEN, D_DIM);

    // Y[b] = att[b] @ V[b]  ==  att[b] @ (Vt[b])^T   (NT)
    dim3 gy(D_DIM / BN, S_LEN / BM, B_BATCH);            // (6,32,4)
    gemm_mma<<<gy, blk, GSMEM>>>(att, Vt, nullptr, Y, D_DIM, S_LEN, SSLL, sd, sd);

    // permutation == per-batch transpose of Y's memory
    transpose_kernel<<<gt, tblk>>>(Y, Yp, S_LEN, D_DIM);

    // output projection -> d_out
    gemm_mma<<<gp, blk, GSMEM>>>(Yp, Wc, bc, out, D_DIM, D_DIM, 0, 0, 0);
}